// round 15
// baseline (speedup 1.0000x reference)
#include <cuda_runtime.h>
#include <cuda_bf16.h>
#include <math.h>
#include <stdint.h>

#define BB 2
#define SS 2048
#define EE 1024
#define HH 16
#define DD 64
#define ROWS (BB*SS)     // 4096
#define KK 1024

// ---------------- scratch (device globals; no allocation) -------------------
__device__ __nv_bfloat16 g_Qhi[BB*HH*SS*DD], g_Qlo[BB*HH*SS*DD];   // [bh][s][d]
__device__ __nv_bfloat16 g_Khi[BB*HH*SS*DD], g_Klo[BB*HH*SS*DD];   // [bh][s][d]
__device__ __nv_bfloat16 g_Vhi[BB*HH*SS*DD], g_Vlo[BB*HH*SS*DD];   // [bh][d][s]
__device__ __nv_bfloat16 g_xhi[ROWS*KK], g_xlo[ROWS*KK];
__device__ __nv_bfloat16 g_cthi[ROWS*KK], g_ctlo[ROWS*KK];
__device__ __nv_bfloat16 g_wqhi[3*EE*KK], g_wqlo[3*EE*KK];   // [N=3072][K]
__device__ __nv_bfloat16 g_wohi[EE*KK],  g_wolo[EE*KK];      // [N=1024][K]

// ---------------- helpers ---------------------------------------------------
__device__ __forceinline__ uint32_t smem_u32(const void* p){
    uint32_t a;
    asm("{ .reg .u64 t; cvta.to.shared.u64 t, %1; cvt.u32.u64 %0, t; }" : "=r"(a) : "l"(p));
    return a;
}
#define SW128(o) ((o) ^ (((o) >> 3) & 0x70))

__device__ __forceinline__ void ldsm4(uint32_t addr, uint32_t& r0, uint32_t& r1,
                                      uint32_t& r2, uint32_t& r3){
    asm volatile("ldmatrix.sync.aligned.m8n8.x4.shared.b16 {%0,%1,%2,%3}, [%4];"
        : "=r"(r0), "=r"(r1), "=r"(r2), "=r"(r3) : "r"(addr));
}
__device__ __forceinline__ void mma_bf16(float* c, const uint32_t* a, const uint32_t* b){
    asm volatile("mma.sync.aligned.m16n8k16.row.col.f32.bf16.bf16.f32 "
        "{%0,%1,%2,%3}, {%4,%5,%6,%7}, {%8,%9}, {%0,%1,%2,%3};"
        : "+f"(c[0]), "+f"(c[1]), "+f"(c[2]), "+f"(c[3])
        : "r"(a[0]), "r"(a[1]), "r"(a[2]), "r"(a[3]), "r"(b[0]), "r"(b[1]));
}
__device__ __forceinline__ uint32_t pack_bf16(float lo, float hi){
    __nv_bfloat162 t = __floats2bfloat162_rn(lo, hi);
    return *(uint32_t*)&t;
}
__device__ __forceinline__ void cp_async16(uint32_t saddr, const void* gptr){
    asm volatile("cp.async.cg.shared.global [%0], [%1], 16;" :: "r"(saddr), "l"(gptr));
}
#define CP_COMMIT() asm volatile("cp.async.commit_group;" ::: "memory")
#define CP_WAIT(N)  asm volatile("cp.async.wait_group %0;" :: "n"(N) : "memory")

__device__ __forceinline__ void ld_afrag(uint32_t base, int wm, int mi, int mr,
                                         int kb, uint32_t a[4][4]){
    #pragma unroll
    for (int fm = 0; fm < 4; fm++) {
        uint32_t off = (uint32_t)((wm + fm*16 + (mi & 1)*8 + mr)*128 + kb + (mi >> 1)*16);
        ldsm4(base + SW128(off), a[fm][0], a[fm][1], a[fm][2], a[fm][3]);
    }
}
__device__ __forceinline__ void ld_bfrag64(uint32_t base, int wn, int mi, int mr,
                                           int kb, uint32_t b[8][2]){
    #pragma unroll
    for (int fn2 = 0; fn2 < 4; fn2++) {
        uint32_t off = (uint32_t)((wn + fn2*16 + (mi >> 1)*8 + mr)*128 + kb + (mi & 1)*16);
        ldsm4(base + SW128(off),
              b[fn2*2][0], b[fn2*2][1], b[fn2*2+1][0], b[fn2*2+1][1]);
    }
}

// ---------------------------------------------------------------------------
// Prep kernels
// ---------------------------------------------------------------------------
__global__ __launch_bounds__(256)
void split_kernel(const float* __restrict__ src, __nv_bfloat16* __restrict__ hi,
                  __nv_bfloat16* __restrict__ lo, int n4)
{
    int i = blockIdx.x * 256 + threadIdx.x;
    if (i >= n4) return;
    float4 v = ((const float4*)src)[i];
    __nv_bfloat16 h[4], l[4];
    float f[4] = {v.x, v.y, v.z, v.w};
    #pragma unroll
    for (int j = 0; j < 4; j++) {
        h[j] = __float2bfloat16(f[j]);
        l[j] = __float2bfloat16(f[j] - __bfloat162float(h[j]));
    }
    ((__nv_bfloat162*)hi)[i*2+0] = __nv_bfloat162(h[0], h[1]);
    ((__nv_bfloat162*)hi)[i*2+1] = __nv_bfloat162(h[2], h[3]);
    ((__nv_bfloat162*)lo)[i*2+0] = __nv_bfloat162(l[0], l[1]);
    ((__nv_bfloat162*)lo)[i*2+1] = __nv_bfloat162(l[2], l[3]);
}

// Fused transpose+split for BOTH weight matrices in one launch.
__global__ __launch_bounds__(256)
void transpose_split2_kernel(const float* __restrict__ Wq, __nv_bfloat16* __restrict__ Tqhi,
                             __nv_bfloat16* __restrict__ Tqlo,
                             const float* __restrict__ Wo, __nv_bfloat16* __restrict__ Tohi,
                             __nv_bfloat16* __restrict__ Tolo)
{
    __shared__ float tile[32][33];
    const bool isQ = blockIdx.x < 96;
    const int nb = isQ ? blockIdx.x : (blockIdx.x - 96);
    const int N  = isQ ? 3*EE : EE;
    const float* W = isQ ? Wq : Wo;
    __nv_bfloat16* Thi = isQ ? Tqhi : Tohi;
    __nv_bfloat16* Tlo = isQ ? Tqlo : Tolo;
    const int n0 = nb * 32, k0 = blockIdx.y * 32;
    const int tx = threadIdx.x & 31, ty = threadIdx.x >> 5;
    #pragma unroll
    for (int i = 0; i < 4; i++)
        tile[ty + 8*i][tx] = W[(size_t)(k0 + ty + 8*i) * N + n0 + tx];
    __syncthreads();
    #pragma unroll
    for (int i = 0; i < 4; i++) {
        float v = tile[tx][ty + 8*i];
        __nv_bfloat16 h = __float2bfloat16(v);
        size_t o = (size_t)(n0 + ty + 8*i) * KK + k0 + tx;
        Thi[o] = h;
        Tlo[o] = __float2bfloat16(v - __bfloat162float(h));
    }
}

// ---------------------------------------------------------------------------
// HMMA bf16x3 GEMM: CTA 128x128, FOUR warps of 64x64 (128 threads),
// 2-stage cp.async. Dyn smem: 2 x (Ahi|Alo|Bhi|Blo, 16KB each) = 128KB.
// Warp 64x64 gives 85 B of ldsm traffic per MMA (vs 128 at 64x32);
// 128 threads keeps the register file per-thread budget spill-free.
// ---------------------------------------------------------------------------
template<int N, bool QKV>
__global__ __launch_bounds__(128)
void gemm_mma_kernel(const __nv_bfloat16* __restrict__ Ahi, const __nv_bfloat16* __restrict__ Alo,
                     const __nv_bfloat16* __restrict__ Bhi, const __nv_bfloat16* __restrict__ Blo,
                     const float* __restrict__ bias, float* __restrict__ C)
{
    extern __shared__ char smem[];
    const uint32_t sb = smem_u32(smem);
    const int tid = threadIdx.x;
    const int wid = tid >> 5;
    const int lane = tid & 31;
    const int m0 = blockIdx.y * 128;
    const int n0 = blockIdx.x * 128;
    const int wm = (wid & 1) * 64;
    const int wn = (wid >> 1) * 64;
    const int mi = lane >> 3;
    const int mr = lane & 7;

    const __nv_bfloat16* srcs[4] = {Ahi, Alo, Bhi, Blo};
    const int rb[4] = {m0, m0, n0, n0};

    auto issue = [&](int chunk, int st){
        const int k0 = chunk * 64;
        const uint32_t stb = sb + st * 65536;
        #pragma unroll
        for (int t = 0; t < 4; t++) {
            #pragma unroll
            for (int i = 0; i < 8; i++) {
                const int idx = i * 128 + tid;      // 0..1023
                const int row = idx >> 3;
                const int cg  = idx & 7;
                cp_async16(stb + t*16384 + SW128((uint32_t)(row*128 + cg*16)),
                           srcs[t] + (size_t)(rb[t] + row) * KK + k0 + cg * 8);
            }
        }
        CP_COMMIT();
    };

    float acc[4][8][4];
    #pragma unroll
    for (int i = 0; i < 4; i++)
        #pragma unroll
        for (int j = 0; j < 8; j++)
            #pragma unroll
            for (int r = 0; r < 4; r++) acc[i][j][r] = 0.0f;

    issue(0, 0);

    const int NC = KK/64;
    for (int chunk = 0; chunk < NC; chunk++) {
        const int st = chunk & 1;
        if (chunk + 1 < NC) { issue(chunk + 1, st ^ 1); CP_WAIT(1); }
        else                { CP_WAIT(0); }
        __syncthreads();

        const uint32_t stb = sb + st * 65536;
        #pragma unroll
        for (int ks = 0; ks < 4; ks++) {
            const int kb = ks * 32;
            uint32_t ah[4][4], al[4][4], bh[8][2], bl[8][2];
            // pass 1 operands
            ld_afrag(stb, wm, mi, mr, kb, ah);
            ld_bfrag64(stb + 32768, wn, mi, mr, kb, bh);
            #pragma unroll
            for (int fm = 0; fm < 4; fm++)
                #pragma unroll
                for (int fn = 0; fn < 8; fn++)
                    mma_bf16(acc[fm][fn], ah[fm], bh[fn]);
            // pass 2
            ld_bfrag64(stb + 49152, wn, mi, mr, kb, bl);
            #pragma unroll
            for (int fm = 0; fm < 4; fm++)
                #pragma unroll
                for (int fn = 0; fn < 8; fn++)
                    mma_bf16(acc[fm][fn], ah[fm], bl[fn]);
            // pass 3
            ld_afrag(stb + 16384, wm, mi, mr, kb, al);
            #pragma unroll
            for (int fm = 0; fm < 4; fm++)
                #pragma unroll
                for (int fn = 0; fn < 8; fn++)
                    mma_bf16(acc[fm][fn], al[fm], bh[fn]);
        }
        __syncthreads();
    }

    #pragma unroll
    for (int fm = 0; fm < 4; fm++) {
        #pragma unroll
        for (int fn = 0; fn < 8; fn++) {
            const int row0 = m0 + wm + fm*16 + (lane >> 2);
            const int col  = n0 + wn + fn*8 + (lane & 3)*2;
            #pragma unroll
            for (int half = 0; half < 2; half++) {
                const int row = row0 + half*8;
                #pragma unroll
                for (int e = 0; e < 2; e++) {
                    const int c = col + e;
                    float v = acc[fm][fn][half*2 + e] + bias[c];
                    if (QKV) {
                        const int b = row >> 11;
                        const int s = row & 2047;
                        const int which = c >> 10;
                        const int h = (c >> 6) & 15;
                        const int dd = c & 63;
                        __nv_bfloat16 vh = __float2bfloat16(v);
                        __nv_bfloat16 vl = __float2bfloat16(v - __bfloat162float(vh));
                        if (which == 2) {
                            const size_t o = ((size_t)((b*HH + h)*DD + dd))*SS + s;
                            g_Vhi[o] = vh; g_Vlo[o] = vl;
                        } else {
                            const size_t o = ((size_t)((b*HH + h)*SS + s))*DD + dd;
                            if (which == 0) { g_Qhi[o] = vh; g_Qlo[o] = vl; }
                            else            { g_Khi[o] = vh; g_Klo[o] = vl; }
                        }
                    } else {
                        C[(size_t)row * N + c] = v;
                    }
                }
            }
        }
    }
}

// ---------------------------------------------------------------------------
// HMMA bf16x3 flash attention — exact R12 config (3-pass QK, 3-pass PV,
// exp/pack pipelined into PV). Dyn smem: 3 x 32KB + mask.
// ---------------------------------------------------------------------------
__global__ __launch_bounds__(256)
void attn_mma_kernel(const int* __restrict__ mask)
{
    extern __shared__ char smem[];
    const uint32_t sb = smem_u32(smem);
    int* mski = (int*)(smem + 98304);

    const int bh = blockIdx.y;
    const int b  = bh >> 4;
    const int hh = bh & 15;
    const int q0 = blockIdx.x * 128;
    const int tid = threadIdx.x, wid = tid >> 5, lane = tid & 31;
    const int mi = lane >> 3, mr = lane & 7;

    {
        const __nv_bfloat16* qh = g_Qhi + ((size_t)bh*SS + q0)*DD;
        const __nv_bfloat16* ql = g_Qlo + ((size_t)bh*SS + q0)*DD;
        #pragma unroll
        for (int i = 0; i < 4; i++) {
            int idx = i*256 + tid;
            int row = idx >> 3, cg = idx & 7;
            uint32_t off = row*128 + cg*16;
            *(uint4*)(smem + SW128(off))         = *(const uint4*)(qh + (size_t)row*DD + cg*8);
            *(uint4*)(smem + 16384 + SW128(off)) = *(const uint4*)(ql + (size_t)row*DD + cg*8);
        }
    }
    __syncthreads();
    uint32_t qh[4][4], ql[4][4];
    #pragma unroll
    for (int kf = 0; kf < 4; kf++) {
        uint32_t off = (uint32_t)((wid*16 + (mi & 1)*8 + mr)*128 + kf*32 + (mi >> 1)*16);
        ldsm4(sb + SW128(off),         qh[kf][0], qh[kf][1], qh[kf][2], qh[kf][3]);
        ldsm4(sb + 16384 + SW128(off), ql[kf][0], ql[kf][1], ql[kf][2], ql[kf][3]);
    }
    __syncthreads();

    const __nv_bfloat16* Khi0 = g_Khi + (size_t)bh*SS*DD;
    const __nv_bfloat16* Klo0 = g_Klo + (size_t)bh*SS*DD;
    const __nv_bfloat16* Vhi0 = g_Vhi + (size_t)bh*DD*SS;
    const __nv_bfloat16* Vlo0 = g_Vlo + (size_t)bh*DD*SS;

    auto issue = [&](int kt, int st){
        const int k0 = kt*64;
        const uint32_t stb = sb + st*32768;
        #pragma unroll
        for (int i = 0; i < 2; i++) {
            int idx = i*256 + tid;
            int row = idx >> 3, cg = idx & 7;
            uint32_t swo = SW128((uint32_t)(row*128 + cg*16));
            cp_async16(stb + swo,         Khi0 + (size_t)(k0+row)*DD + cg*8);
            cp_async16(stb + 8192 + swo,  Klo0 + (size_t)(k0+row)*DD + cg*8);
            cp_async16(stb + 16384 + swo, Vhi0 + (size_t)row*SS + k0 + cg*8);
            cp_async16(stb + 24576 + swo, Vlo0 + (size_t)row*SS + k0 + cg*8);
        }
        if (tid < 16)
            cp_async16(sb + 98304 + st*256 + tid*16, mask + b*SS + k0 + tid*4);
        CP_COMMIT();
    };

    float O[8][4];
    #pragma unroll
    for (int fn = 0; fn < 8; fn++)
        #pragma unroll
        for (int r = 0; r < 4; r++) O[fn][r] = 0.0f;
    float m_prev[2] = {-1e30f, -1e30f}, l_prev[2] = {0.0f, 0.0f};

    issue(0, 0);
    issue(1, 1);

    const int NT = SS/64;
    int st = 0;
    for (int kt = 0; kt < NT; kt++) {
        CP_WAIT(1);
        __syncthreads();
        if (kt + 2 < NT) {
            int st2 = st + 2; if (st2 >= 3) st2 -= 3;
            issue(kt + 2, st2);
        }
        const uint32_t stb = sb + st*32768;
        const int* mst = mski + st*64;

        float S[8][4];
        #pragma unroll
        for (int fn = 0; fn < 8; fn++)
            #pragma unroll
            for (int r = 0; r < 4; r++) S[fn][r] = 0.0f;

        #pragma unroll
        for (int kf = 0; kf < 4; kf++) {
            uint32_t kh[8][2], kl[8][2];
            ld_bfrag64(stb,        0, mi, mr, kf*32, kh);
            ld_bfrag64(stb + 8192, 0, mi, mr, kf*32, kl);
            #pragma unroll
            for (int fn = 0; fn < 8; fn++) {
                mma_bf16(S[fn], qh[kf], kh[fn]);
                mma_bf16(S[fn], qh[kf], kl[fn]);
                mma_bf16(S[fn], ql[kf], kh[fn]);
            }
        }

        #pragma unroll
        for (int fn = 0; fn < 8; fn++) {
            const int c0 = fn*8 + (lane & 3)*2;
            const float b0 = mst[c0]   ? 0.0f : -1e30f;
            const float b1 = mst[c0+1] ? 0.0f : -1e30f;
            S[fn][0] = S[fn][0]*0.125f + b0;
            S[fn][1] = S[fn][1]*0.125f + b1;
            S[fn][2] = S[fn][2]*0.125f + b0;
            S[fn][3] = S[fn][3]*0.125f + b1;
        }

        float mnew[2], alpha[2];
        #pragma unroll
        for (int h = 0; h < 2; h++) {
            float mx = -1e30f;
            #pragma unroll
            for (int fn = 0; fn < 8; fn++)
                mx = fmaxf(mx, fmaxf(S[fn][h*2], S[fn][h*2+1]));
            mx = fmaxf(mx, __shfl_xor_sync(0xffffffffu, mx, 1));
            mx = fmaxf(mx, __shfl_xor_sync(0xffffffffu, mx, 2));
            mnew[h] = fmaxf(m_prev[h], mx);
            alpha[h] = __expf(m_prev[h] - mnew[h]);
            m_prev[h] = mnew[h];
        }
        #pragma unroll
        for (int fn = 0; fn < 8; fn++) {
            O[fn][0] *= alpha[0]; O[fn][1] *= alpha[0];
            O[fn][2] *= alpha[1]; O[fn][3] *= alpha[1];
        }

        float ls[2] = {0.0f, 0.0f};
        #pragma unroll
        for (int kf = 0; kf < 4; kf++) {
            uint32_t vh[8][2], vl[8][2];
            ld_bfrag64(stb + 16384, 0, mi, mr, kf*32, vh);
            ld_bfrag64(stb + 24576, 0, mi, mr, kf*32, vl);
            uint32_t phi[4], plo[4];
            {
                float* s0 = S[2*kf];
                float* s1 = S[2*kf + 1];
                float p[8];
                p[0] = __expf(s0[0] - mnew[0]); p[1] = __expf(s0[1] - mnew[0]);
                p[2] = __expf(s0[2] - mnew[1]); p[3] = __expf(s0[3] - mnew[1]);
                p[4] = __expf(s1[0] - mnew[0]); p[5] = __expf(s1[1] - mnew[0]);
                p[6] = __expf(s1[2] - mnew[1]); p[7] = __expf(s1[3] - mnew[1]);
                ls[0] += (p[0] + p[1]) + (p[4] + p[5]);
                ls[1] += (p[2] + p[3]) + (p[6] + p[7]);
                float h[8], l[8];
                #pragma unroll
                for (int e = 0; e < 8; e++) {
                    __nv_bfloat16 t = __float2bfloat16(p[e]);
                    h[e] = __bfloat162float(t);
                    l[e] = p[e] - h[e];
                }
                phi[0] = pack_bf16(h[0], h[1]); phi[1] = pack_bf16(h[2], h[3]);
                phi[2] = pack_bf16(h[4], h[5]); phi[3] = pack_bf16(h[6], h[7]);
                plo[0] = pack_bf16(l[0], l[1]); plo[1] = pack_bf16(l[2], l[3]);
                plo[2] = pack_bf16(l[4], l[5]); plo[3] = pack_bf16(l[6], l[7]);
            }
            #pragma unroll
            for (int fn = 0; fn < 8; fn++) {
                mma_bf16(O[fn], phi, vh[fn]);
                mma_bf16(O[fn], phi, vl[fn]);
                mma_bf16(O[fn], plo, vh[fn]);
            }
        }
        #pragma unroll
        for (int h = 0; h < 2; h++) {
            float s = ls[h];
            s += __shfl_xor_sync(0xffffffffu, s, 1);
            s += __shfl_xor_sync(0xffffffffu, s, 2);
            l_prev[h] = l_prev[h]*alpha[h] + s;
        }
        if (++st >= 3) st = 0;
    }

    const float inv0 = 1.0f / l_prev[0];
    const float inv1 = 1.0f / l_prev[1];
    const int row0 = q0 + wid*16 + (lane >> 2);
    #pragma unroll
    for (int fn = 0; fn < 8; fn++) {
        const int dcol = fn*8 + (lane & 3)*2;
        const size_t o0 = (size_t)(b*SS + row0)*EE + hh*DD + dcol;
        const size_t o1 = (size_t)(b*SS + row0 + 8)*EE + hh*DD + dcol;
        float v00 = O[fn][0]*inv0, v01 = O[fn][1]*inv0;
        float v10 = O[fn][2]*inv1, v11 = O[fn][3]*inv1;
        __nv_bfloat16 h;
        h = __float2bfloat16(v00); g_cthi[o0]   = h; g_ctlo[o0]   = __float2bfloat16(v00 - __bfloat162float(h));
        h = __float2bfloat16(v01); g_cthi[o0+1] = h; g_ctlo[o0+1] = __float2bfloat16(v01 - __bfloat162float(h));
        h = __float2bfloat16(v10); g_cthi[o1]   = h; g_ctlo[o1]   = __float2bfloat16(v10 - __bfloat162float(h));
        h = __float2bfloat16(v11); g_cthi[o1+1] = h; g_ctlo[o1+1] = __float2bfloat16(v11 - __bfloat162float(h));
    }
}

// ---------------------------------------------------------------------------
extern "C" void kernel_launch(void* const* d_in, const int* in_sizes, int n_in,
                              void* d_out, int out_size)
{
    const float* x    = (const float*)d_in[0];
    const int*   mask = (const int*)  d_in[1];
    const float* Wqkv = (const float*)d_in[2];
    const float* bqkv = (const float*)d_in[3];
    const float* Wout = (const float*)d_in[4];
    const float* bout = (const float*)d_in[5];
    float* out = (float*)d_out;

    __nv_bfloat16 *xhi, *xlo, *cthi, *ctlo, *wqhi, *wqlo, *wohi, *wolo;
    cudaGetSymbolAddress((void**)&xhi,  g_xhi);
    cudaGetSymbolAddress((void**)&xlo,  g_xlo);
    cudaGetSymbolAddress((void**)&cthi, g_cthi);
    cudaGetSymbolAddress((void**)&ctlo, g_ctlo);
    cudaGetSymbolAddress((void**)&wqhi, g_wqhi);
    cudaGetSymbolAddress((void**)&wqlo, g_wqlo);
    cudaGetSymbolAddress((void**)&wohi, g_wohi);
    cudaGetSymbolAddress((void**)&wolo, g_wolo);

    const int gemm_smem = 2 * 65536;          // 128KB
    const int attn_smem = 3 * 32768 + 768;    // 96KB + mask
    cudaFuncSetAttribute(gemm_mma_kernel<3*EE, true>,
                         cudaFuncAttributeMaxDynamicSharedMemorySize, gemm_smem);
    cudaFuncSetAttribute(gemm_mma_kernel<EE, false>,
                         cudaFuncAttributeMaxDynamicSharedMemorySize, gemm_smem);
    cudaFuncSetAttribute(attn_mma_kernel,
                         cudaFuncAttributeMaxDynamicSharedMemorySize, attn_smem);

    // prep
    split_kernel<<<ROWS*KK/4/256, 256>>>(x, xhi, xlo, ROWS*KK/4);
    transpose_split2_kernel<<<dim3(128, KK/32), 256>>>(Wqkv, wqhi, wqlo, Wout, wohi, wolo);

    // 1) QKV projection (HMMA, 4-warp 64x64 tiles) + split/scatter epilogue
    gemm_mma_kernel<3*EE, true><<<dim3(3*EE/128, ROWS/128), 128, gemm_smem>>>(
        xhi, xlo, wqhi, wqlo, bqkv, nullptr);

    // 2) attention (HMMA bf16x3 flash, R12 proven config)
    attn_mma_kernel<<<dim3(SS/128, BB*HH), 256, attn_smem>>>(mask);

    // 3) output projection (HMMA, 4-warp 64x64 tiles)
    gemm_mma_kernel<EE, false><<<dim3(EE/128, ROWS/128), 128, gemm_smem>>>(
        cthi, ctlo, wohi, wolo, bout, out);
}

// round 16
// speedup vs baseline: 1.1128x; 1.1128x over previous
#include <cuda_runtime.h>
#include <cuda_bf16.h>
#include <math.h>
#include <stdint.h>

#define BB 2
#define SS 2048
#define EE 1024
#define HH 16
#define DD 64
#define ROWS (BB*SS)     // 4096
#define KK 1024

// ---------------- scratch (device globals; no allocation) -------------------
__device__ __nv_bfloat16 g_Qhi[BB*HH*SS*DD], g_Qlo[BB*HH*SS*DD];   // [bh][s][d]
__device__ __nv_bfloat16 g_Khi[BB*HH*SS*DD], g_Klo[BB*HH*SS*DD];   // [bh][s][d]
__device__ __nv_bfloat16 g_Vhi[BB*HH*SS*DD], g_Vlo[BB*HH*SS*DD];   // [bh][d][s]
__device__ __nv_bfloat16 g_xhi[ROWS*KK], g_xlo[ROWS*KK];
__device__ __nv_bfloat16 g_cthi[ROWS*KK], g_ctlo[ROWS*KK];
__device__ __nv_bfloat16 g_wqhi[3*EE*KK], g_wqlo[3*EE*KK];   // [N=3072][K]
__device__ __nv_bfloat16 g_wohi[EE*KK],  g_wolo[EE*KK];      // [N=1024][K]

// ---------------- helpers ---------------------------------------------------
__device__ __forceinline__ uint32_t smem_u32(const void* p){
    uint32_t a;
    asm("{ .reg .u64 t; cvta.to.shared.u64 t, %1; cvt.u32.u64 %0, t; }" : "=r"(a) : "l"(p));
    return a;
}
#define SW128(o) ((o) ^ (((o) >> 3) & 0x70))

__device__ __forceinline__ void ldsm4(uint32_t addr, uint32_t& r0, uint32_t& r1,
                                      uint32_t& r2, uint32_t& r3){
    asm volatile("ldmatrix.sync.aligned.m8n8.x4.shared.b16 {%0,%1,%2,%3}, [%4];"
        : "=r"(r0), "=r"(r1), "=r"(r2), "=r"(r3) : "r"(addr));
}
__device__ __forceinline__ void mma_bf16(float* c, const uint32_t* a, const uint32_t* b){
    asm volatile("mma.sync.aligned.m16n8k16.row.col.f32.bf16.bf16.f32 "
        "{%0,%1,%2,%3}, {%4,%5,%6,%7}, {%8,%9}, {%0,%1,%2,%3};"
        : "+f"(c[0]), "+f"(c[1]), "+f"(c[2]), "+f"(c[3])
        : "r"(a[0]), "r"(a[1]), "r"(a[2]), "r"(a[3]), "r"(b[0]), "r"(b[1]));
}
__device__ __forceinline__ uint32_t pack_bf16(float lo, float hi){
    __nv_bfloat162 t = __floats2bfloat162_rn(lo, hi);
    return *(uint32_t*)&t;
}
__device__ __forceinline__ void cp_async16(uint32_t saddr, const void* gptr){
    asm volatile("cp.async.cg.shared.global [%0], [%1], 16;" :: "r"(saddr), "l"(gptr));
}
#define CP_COMMIT() asm volatile("cp.async.commit_group;" ::: "memory")
#define CP_WAIT(N)  asm volatile("cp.async.wait_group %0;" :: "n"(N) : "memory")

__device__ __forceinline__ void ld_afrag(uint32_t base, int wm, int mi, int mr,
                                         int kb, uint32_t a[4][4]){
    #pragma unroll
    for (int fm = 0; fm < 4; fm++) {
        uint32_t off = (uint32_t)((wm + fm*16 + (mi & 1)*8 + mr)*128 + kb + (mi >> 1)*16);
        ldsm4(base + SW128(off), a[fm][0], a[fm][1], a[fm][2], a[fm][3]);
    }
}
__device__ __forceinline__ void ld_bfrag32(uint32_t base, int wn, int mi, int mr,
                                           int kb, uint32_t b[4][2]){
    #pragma unroll
    for (int fn2 = 0; fn2 < 2; fn2++) {
        uint32_t off = (uint32_t)((wn + fn2*16 + (mi >> 1)*8 + mr)*128 + kb + (mi & 1)*16);
        ldsm4(base + SW128(off),
              b[fn2*2][0], b[fn2*2][1], b[fn2*2+1][0], b[fn2*2+1][1]);
    }
}
__device__ __forceinline__ void ld_bfrag64(uint32_t base, int mi, int mr,
                                           int kb, uint32_t b[8][2]){
    #pragma unroll
    for (int fn2 = 0; fn2 < 4; fn2++) {
        uint32_t off = (uint32_t)((fn2*16 + (mi >> 1)*8 + mr)*128 + kb + (mi & 1)*16);
        ldsm4(base + SW128(off),
              b[fn2*2][0], b[fn2*2][1], b[fn2*2+1][0], b[fn2*2+1][1]);
    }
}

// ---------------------------------------------------------------------------
// Prep kernels
// ---------------------------------------------------------------------------
__global__ __launch_bounds__(256)
void split_kernel(const float* __restrict__ src, __nv_bfloat16* __restrict__ hi,
                  __nv_bfloat16* __restrict__ lo, int n4)
{
    int i = blockIdx.x * 256 + threadIdx.x;
    if (i >= n4) return;
    float4 v = ((const float4*)src)[i];
    __nv_bfloat16 h[4], l[4];
    float f[4] = {v.x, v.y, v.z, v.w};
    #pragma unroll
    for (int j = 0; j < 4; j++) {
        h[j] = __float2bfloat16(f[j]);
        l[j] = __float2bfloat16(f[j] - __bfloat162float(h[j]));
    }
    ((__nv_bfloat162*)hi)[i*2+0] = __nv_bfloat162(h[0], h[1]);
    ((__nv_bfloat162*)hi)[i*2+1] = __nv_bfloat162(h[2], h[3]);
    ((__nv_bfloat162*)lo)[i*2+0] = __nv_bfloat162(l[0], l[1]);
    ((__nv_bfloat162*)lo)[i*2+1] = __nv_bfloat162(l[2], l[3]);
}

// Fused transpose+split for BOTH weight matrices in one launch.
__global__ __launch_bounds__(256)
void transpose_split2_kernel(const float* __restrict__ Wq, __nv_bfloat16* __restrict__ Tqhi,
                             __nv_bfloat16* __restrict__ Tqlo,
                             const float* __restrict__ Wo, __nv_bfloat16* __restrict__ Tohi,
                             __nv_bfloat16* __restrict__ Tolo)
{
    __shared__ float tile[32][33];
    const bool isQ = blockIdx.x < 96;
    const int nb = isQ ? blockIdx.x : (blockIdx.x - 96);
    const int N  = isQ ? 3*EE : EE;
    const float* W = isQ ? Wq : Wo;
    __nv_bfloat16* Thi = isQ ? Tqhi : Tohi;
    __nv_bfloat16* Tlo = isQ ? Tqlo : Tolo;
    const int n0 = nb * 32, k0 = blockIdx.y * 32;
    const int tx = threadIdx.x & 31, ty = threadIdx.x >> 5;
    #pragma unroll
    for (int i = 0; i < 4; i++)
        tile[ty + 8*i][tx] = W[(size_t)(k0 + ty + 8*i) * N + n0 + tx];
    __syncthreads();
    #pragma unroll
    for (int i = 0; i < 4; i++) {
        float v = tile[tx][ty + 8*i];
        __nv_bfloat16 h = __float2bfloat16(v);
        size_t o = (size_t)(n0 + ty + 8*i) * KK + k0 + tx;
        Thi[o] = h;
        Tlo[o] = __float2bfloat16(v - __bfloat162float(h));
    }
}

// ---------------------------------------------------------------------------
// HMMA bf16x3 GEMM: CTA 128x128, warp 64x32, SINGLE 64KB stage,
// __launch_bounds__(256, 2) -> 2 CTAs/SM; inter-CTA overlap replaces
// intra-CTA double buffering.
// ---------------------------------------------------------------------------
template<int N, bool QKV>
__global__ __launch_bounds__(256, 2)
void gemm_mma_kernel(const __nv_bfloat16* __restrict__ Ahi, const __nv_bfloat16* __restrict__ Alo,
                     const __nv_bfloat16* __restrict__ Bhi, const __nv_bfloat16* __restrict__ Blo,
                     const float* __restrict__ bias, float* __restrict__ C)
{
    extern __shared__ char smem[];
    const uint32_t sb = smem_u32(smem);
    const int tid = threadIdx.x;
    const int wid = tid >> 5;
    const int lane = tid & 31;
    const int m0 = blockIdx.y * 128;
    const int n0 = blockIdx.x * 128;
    const int wm = (wid & 1) * 64;
    const int wn = (wid >> 1) * 32;
    const int mi = lane >> 3;
    const int mr = lane & 7;

    const __nv_bfloat16* srcs[4] = {Ahi, Alo, Bhi, Blo};
    const int rb[4] = {m0, m0, n0, n0};

    auto issue = [&](int chunk){
        const int k0 = chunk * 64;
        #pragma unroll
        for (int t = 0; t < 4; t++) {
            #pragma unroll
            for (int i = 0; i < 4; i++) {
                const int idx = i * 256 + tid;
                const int row = idx >> 3;
                const int cg  = idx & 7;
                cp_async16(sb + t*16384 + SW128((uint32_t)(row*128 + cg*16)),
                           srcs[t] + (size_t)(rb[t] + row) * KK + k0 + cg * 8);
            }
        }
        CP_COMMIT();
    };

    float acc[4][4][4];
    #pragma unroll
    for (int i = 0; i < 4; i++)
        #pragma unroll
        for (int j = 0; j < 4; j++)
            #pragma unroll
            for (int r = 0; r < 4; r++) acc[i][j][r] = 0.0f;

    const int NC = KK/64;
    for (int chunk = 0; chunk < NC; chunk++) {
        issue(chunk);
        CP_WAIT(0);
        __syncthreads();

        #pragma unroll
        for (int ks = 0; ks < 4; ks++) {
            const int kb = ks * 32;
            uint32_t ah[4][4], al[4][4], bh[4][2], bl[4][2];
            ld_afrag(sb, wm, mi, mr, kb, ah);
            ld_bfrag32(sb + 32768, wn, mi, mr, kb, bh);
            #pragma unroll
            for (int fm = 0; fm < 4; fm++)
                #pragma unroll
                for (int fn = 0; fn < 4; fn++)
                    mma_bf16(acc[fm][fn], ah[fm], bh[fn]);
            ld_bfrag32(sb + 49152, wn, mi, mr, kb, bl);
            #pragma unroll
            for (int fm = 0; fm < 4; fm++)
                #pragma unroll
                for (int fn = 0; fn < 4; fn++)
                    mma_bf16(acc[fm][fn], ah[fm], bl[fn]);
            ld_afrag(sb + 16384, wm, mi, mr, kb, al);
            #pragma unroll
            for (int fm = 0; fm < 4; fm++)
                #pragma unroll
                for (int fn = 0; fn < 4; fn++)
                    mma_bf16(acc[fm][fn], al[fm], bh[fn]);
        }
        __syncthreads();
    }

    #pragma unroll
    for (int fm = 0; fm < 4; fm++) {
        #pragma unroll
        for (int fn = 0; fn < 4; fn++) {
            const int row0 = m0 + wm + fm*16 + (lane >> 2);
            const int col  = n0 + wn + fn*8 + (lane & 3)*2;
            #pragma unroll
            for (int half = 0; half < 2; half++) {
                const int row = row0 + half*8;
                #pragma unroll
                for (int e = 0; e < 2; e++) {
                    const int c = col + e;
                    float v = acc[fm][fn][half*2 + e] + bias[c];
                    if (QKV) {
                        const int b = row >> 11;
                        const int s = row & 2047;
                        const int which = c >> 10;
                        const int h = (c >> 6) & 15;
                        const int dd = c & 63;
                        __nv_bfloat16 vh = __float2bfloat16(v);
                        __nv_bfloat16 vl = __float2bfloat16(v - __bfloat162float(vh));
                        if (which == 2) {
                            const size_t o = ((size_t)((b*HH + h)*DD + dd))*SS + s;
                            g_Vhi[o] = vh; g_Vlo[o] = vl;
                        } else {
                            const size_t o = ((size_t)((b*HH + h)*SS + s))*DD + dd;
                            if (which == 0) { g_Qhi[o] = vh; g_Qlo[o] = vl; }
                            else            { g_Khi[o] = vh; g_Klo[o] = vl; }
                        }
                    } else {
                        C[(size_t)row * N + c] = v;
                    }
                }
            }
        }
    }
}

// ---------------------------------------------------------------------------
// HMMA bf16x3 flash attention — exact R12 config (3-pass QK, 3-pass PV,
// exp/pack pipelined into PV). Dyn smem: 3 x 32KB + mask.
// ---------------------------------------------------------------------------
__global__ __launch_bounds__(256)
void attn_mma_kernel(const int* __restrict__ mask)
{
    extern __shared__ char smem[];
    const uint32_t sb = smem_u32(smem);
    int* mski = (int*)(smem + 98304);

    const int bh = blockIdx.y;
    const int b  = bh >> 4;
    const int hh = bh & 15;
    const int q0 = blockIdx.x * 128;
    const int tid = threadIdx.x, wid = tid >> 5, lane = tid & 31;
    const int mi = lane >> 3, mr = lane & 7;

    {
        const __nv_bfloat16* qh = g_Qhi + ((size_t)bh*SS + q0)*DD;
        const __nv_bfloat16* ql = g_Qlo + ((size_t)bh*SS + q0)*DD;
        #pragma unroll
        for (int i = 0; i < 4; i++) {
            int idx = i*256 + tid;
            int row = idx >> 3, cg = idx & 7;
            uint32_t off = row*128 + cg*16;
            *(uint4*)(smem + SW128(off))         = *(const uint4*)(qh + (size_t)row*DD + cg*8);
            *(uint4*)(smem + 16384 + SW128(off)) = *(const uint4*)(ql + (size_t)row*DD + cg*8);
        }
    }
    __syncthreads();
    uint32_t qh[4][4], ql[4][4];
    #pragma unroll
    for (int kf = 0; kf < 4; kf++) {
        uint32_t off = (uint32_t)((wid*16 + (mi & 1)*8 + mr)*128 + kf*32 + (mi >> 1)*16);
        ldsm4(sb + SW128(off),         qh[kf][0], qh[kf][1], qh[kf][2], qh[kf][3]);
        ldsm4(sb + 16384 + SW128(off), ql[kf][0], ql[kf][1], ql[kf][2], ql[kf][3]);
    }
    __syncthreads();

    const __nv_bfloat16* Khi0 = g_Khi + (size_t)bh*SS*DD;
    const __nv_bfloat16* Klo0 = g_Klo + (size_t)bh*SS*DD;
    const __nv_bfloat16* Vhi0 = g_Vhi + (size_t)bh*DD*SS;
    const __nv_bfloat16* Vlo0 = g_Vlo + (size_t)bh*DD*SS;

    auto issue = [&](int kt, int st){
        const int k0 = kt*64;
        const uint32_t stb = sb + st*32768;
        #pragma unroll
        for (int i = 0; i < 2; i++) {
            int idx = i*256 + tid;
            int row = idx >> 3, cg = idx & 7;
            uint32_t swo = SW128((uint32_t)(row*128 + cg*16));
            cp_async16(stb + swo,         Khi0 + (size_t)(k0+row)*DD + cg*8);
            cp_async16(stb + 8192 + swo,  Klo0 + (size_t)(k0+row)*DD + cg*8);
            cp_async16(stb + 16384 + swo, Vhi0 + (size_t)row*SS + k0 + cg*8);
            cp_async16(stb + 24576 + swo, Vlo0 + (size_t)row*SS + k0 + cg*8);
        }
        if (tid < 16)
            cp_async16(sb + 98304 + st*256 + tid*16, mask + b*SS + k0 + tid*4);
        CP_COMMIT();
    };

    float O[8][4];
    #pragma unroll
    for (int fn = 0; fn < 8; fn++)
        #pragma unroll
        for (int r = 0; r < 4; r++) O[fn][r] = 0.0f;
    float m_prev[2] = {-1e30f, -1e30f}, l_prev[2] = {0.0f, 0.0f};

    issue(0, 0);
    issue(1, 1);

    const int NT = SS/64;
    int st = 0;
    for (int kt = 0; kt < NT; kt++) {
        CP_WAIT(1);
        __syncthreads();
        if (kt + 2 < NT) {
            int st2 = st + 2; if (st2 >= 3) st2 -= 3;
            issue(kt + 2, st2);
        }
        const uint32_t stb = sb + st*32768;
        const int* mst = mski + st*64;

        float S[8][4];
        #pragma unroll
        for (int fn = 0; fn < 8; fn++)
            #pragma unroll
            for (int r = 0; r < 4; r++) S[fn][r] = 0.0f;

        #pragma unroll
        for (int kf = 0; kf < 4; kf++) {
            uint32_t kh[8][2], kl[8][2];
            ld_bfrag64(stb,        mi, mr, kf*32, kh);
            ld_bfrag64(stb + 8192, mi, mr, kf*32, kl);
            #pragma unroll
            for (int fn = 0; fn < 8; fn++) {
                mma_bf16(S[fn], qh[kf], kh[fn]);
                mma_bf16(S[fn], qh[kf], kl[fn]);
                mma_bf16(S[fn], ql[kf], kh[fn]);
            }
        }

        #pragma unroll
        for (int fn = 0; fn < 8; fn++) {
            const int c0 = fn*8 + (lane & 3)*2;
            const float b0 = mst[c0]   ? 0.0f : -1e30f;
            const float b1 = mst[c0+1] ? 0.0f : -1e30f;
            S[fn][0] = S[fn][0]*0.125f + b0;
            S[fn][1] = S[fn][1]*0.125f + b1;
            S[fn][2] = S[fn][2]*0.125f + b0;
            S[fn][3] = S[fn][3]*0.125f + b1;
        }

        float mnew[2], alpha[2];
        #pragma unroll
        for (int h = 0; h < 2; h++) {
            float mx = -1e30f;
            #pragma unroll
            for (int fn = 0; fn < 8; fn++)
                mx = fmaxf(mx, fmaxf(S[fn][h*2], S[fn][h*2+1]));
            mx = fmaxf(mx, __shfl_xor_sync(0xffffffffu, mx, 1));
            mx = fmaxf(mx, __shfl_xor_sync(0xffffffffu, mx, 2));
            mnew[h] = fmaxf(m_prev[h], mx);
            alpha[h] = __expf(m_prev[h] - mnew[h]);
            m_prev[h] = mnew[h];
        }
        #pragma unroll
        for (int fn = 0; fn < 8; fn++) {
            O[fn][0] *= alpha[0]; O[fn][1] *= alpha[0];
            O[fn][2] *= alpha[1]; O[fn][3] *= alpha[1];
        }

        float ls[2] = {0.0f, 0.0f};
        #pragma unroll
        for (int kf = 0; kf < 4; kf++) {
            uint32_t vh[8][2], vl[8][2];
            ld_bfrag64(stb + 16384, mi, mr, kf*32, vh);
            ld_bfrag64(stb + 24576, mi, mr, kf*32, vl);
            uint32_t phi[4], plo[4];
            {
                float* s0 = S[2*kf];
                float* s1 = S[2*kf + 1];
                float p[8];
                p[0] = __expf(s0[0] - mnew[0]); p[1] = __expf(s0[1] - mnew[0]);
                p[2] = __expf(s0[2] - mnew[1]); p[3] = __expf(s0[3] - mnew[1]);
                p[4] = __expf(s1[0] - mnew[0]); p[5] = __expf(s1[1] - mnew[0]);
                p[6] = __expf(s1[2] - mnew[1]); p[7] = __expf(s1[3] - mnew[1]);
                ls[0] += (p[0] + p[1]) + (p[4] + p[5]);
                ls[1] += (p[2] + p[3]) + (p[6] + p[7]);
                float h[8], l[8];
                #pragma unroll
                for (int e = 0; e < 8; e++) {
                    __nv_bfloat16 t = __float2bfloat16(p[e]);
                    h[e] = __bfloat162float(t);
                    l[e] = p[e] - h[e];
                }
                phi[0] = pack_bf16(h[0], h[1]); phi[1] = pack_bf16(h[2], h[3]);
                phi[2] = pack_bf16(h[4], h[5]); phi[3] = pack_bf16(h[6], h[7]);
                plo[0] = pack_bf16(l[0], l[1]); plo[1] = pack_bf16(l[2], l[3]);
                plo[2] = pack_bf16(l[4], l[5]); plo[3] = pack_bf16(l[6], l[7]);
            }
            #pragma unroll
            for (int fn = 0; fn < 8; fn++) {
                mma_bf16(O[fn], phi, vh[fn]);
                mma_bf16(O[fn], phi, vl[fn]);
                mma_bf16(O[fn], plo, vh[fn]);
            }
        }
        #pragma unroll
        for (int h = 0; h < 2; h++) {
            float s = ls[h];
            s += __shfl_xor_sync(0xffffffffu, s, 1);
            s += __shfl_xor_sync(0xffffffffu, s, 2);
            l_prev[h] = l_prev[h]*alpha[h] + s;
        }
        if (++st >= 3) st = 0;
    }

    const float inv0 = 1.0f / l_prev[0];
    const float inv1 = 1.0f / l_prev[1];
    const int row0 = q0 + wid*16 + (lane >> 2);
    #pragma unroll
    for (int fn = 0; fn < 8; fn++) {
        const int dcol = fn*8 + (lane & 3)*2;
        const size_t o0 = (size_t)(b*SS + row0)*EE + hh*DD + dcol;
        const size_t o1 = (size_t)(b*SS + row0 + 8)*EE + hh*DD + dcol;
        float v00 = O[fn][0]*inv0, v01 = O[fn][1]*inv0;
        float v10 = O[fn][2]*inv1, v11 = O[fn][3]*inv1;
        __nv_bfloat16 h;
        h = __float2bfloat16(v00); g_cthi[o0]   = h; g_ctlo[o0]   = __float2bfloat16(v00 - __bfloat162float(h));
        h = __float2bfloat16(v01); g_cthi[o0+1] = h; g_ctlo[o0+1] = __float2bfloat16(v01 - __bfloat162float(h));
        h = __float2bfloat16(v10); g_cthi[o1]   = h; g_ctlo[o1]   = __float2bfloat16(v10 - __bfloat162float(h));
        h = __float2bfloat16(v11); g_cthi[o1+1] = h; g_ctlo[o1+1] = __float2bfloat16(v11 - __bfloat162float(h));
    }
}

// ---------------------------------------------------------------------------
extern "C" void kernel_launch(void* const* d_in, const int* in_sizes, int n_in,
                              void* d_out, int out_size)
{
    const float* x    = (const float*)d_in[0];
    const int*   mask = (const int*)  d_in[1];
    const float* Wqkv = (const float*)d_in[2];
    const float* bqkv = (const float*)d_in[3];
    const float* Wout = (const float*)d_in[4];
    const float* bout = (const float*)d_in[5];
    float* out = (float*)d_out;

    __nv_bfloat16 *xhi, *xlo, *cthi, *ctlo, *wqhi, *wqlo, *wohi, *wolo;
    cudaGetSymbolAddress((void**)&xhi,  g_xhi);
    cudaGetSymbolAddress((void**)&xlo,  g_xlo);
    cudaGetSymbolAddress((void**)&cthi, g_cthi);
    cudaGetSymbolAddress((void**)&ctlo, g_ctlo);
    cudaGetSymbolAddress((void**)&wqhi, g_wqhi);
    cudaGetSymbolAddress((void**)&wqlo, g_wqlo);
    cudaGetSymbolAddress((void**)&wohi, g_wohi);
    cudaGetSymbolAddress((void**)&wolo, g_wolo);

    const int gemm_smem = 65536;              // 64KB single stage, 2 CTAs/SM
    const int attn_smem = 3 * 32768 + 768;    // 96KB + mask
    cudaFuncSetAttribute(gemm_mma_kernel<3*EE, true>,
                         cudaFuncAttributeMaxDynamicSharedMemorySize, gemm_smem);
    cudaFuncSetAttribute(gemm_mma_kernel<EE, false>,
                         cudaFuncAttributeMaxDynamicSharedMemorySize, gemm_smem);
    cudaFuncSetAttribute(attn_mma_kernel,
                         cudaFuncAttributeMaxDynamicSharedMemorySize, attn_smem);

    // prep
    split_kernel<<<ROWS*KK/4/256, 256>>>(x, xhi, xlo, ROWS*KK/4);
    transpose_split2_kernel<<<dim3(128, KK/32), 256>>>(Wqkv, wqhi, wqlo, Wout, wohi, wolo);

    // 1) QKV projection (HMMA, 2 CTAs/SM) + split/scatter epilogue
    gemm_mma_kernel<3*EE, true><<<dim3(3*EE/128, ROWS/128), 256, gemm_smem>>>(
        xhi, xlo, wqhi, wqlo, bqkv, nullptr);

    // 2) attention (HMMA bf16x3 flash, R12 proven config)
    attn_mma_kernel<<<dim3(SS/128, BB*HH), 256, attn_smem>>>(mask);

    // 3) output projection (HMMA, 2 CTAs/SM)
    gemm_mma_kernel<EE, false><<<dim3(EE/128, ROWS/128), 256, gemm_smem>>>(
        cthi, ctlo, wohi, wolo, bout, out);
}